// round 2
// baseline (speedup 1.0000x reference)
#include <cuda_runtime.h>
#include <math.h>

// TensorProductLayer fused kernel (fp32, f32x2-packed FFMA).
//
//   h   = silu(radial @ W1 + b1)                       [N, 64]
//   w   = (h @ W2 + b2).reshape(N, 64, 64)
//   out = einsum('ni,nio->no', features, w) * (angular @ Wa + ba)
//
// Restructured as a single fused GEMM: out = U @ W2' (+ F @ b2') with
// U[n, h*64+i] = h[n,h] * f[n,i] built on the fly per 64-wide K-chunk.
// Bias folds in as a 65th chunk with h == 1.

#define NTOK    65536
#define TILE_T  128
#define THREADS 256
#define FSTR    132          // padded smem stride (floats), 16B aligned, de-conflicted
#define SMEM_FLOATS (2 * 64 * FSTR + 2 * 4096)
#define SMEM_BYTES  (SMEM_FLOATS * 4)

static __device__ __forceinline__ unsigned long long dup2(float x) {
    unsigned long long r;
    asm("mov.b64 %0, {%1, %1};" : "=l"(r) : "f"(x));
    return r;
}
static __device__ __forceinline__ unsigned long long mul2(unsigned long long a, unsigned long long b) {
    unsigned long long d;
    asm("mul.rn.f32x2 %0, %1, %2;" : "=l"(d) : "l"(a), "l"(b));
    return d;
}
static __device__ __forceinline__ void fma2(unsigned long long& d, unsigned long long a, unsigned long long b) {
    asm("fma.rn.f32x2 %0, %1, %2, %3;" : "=l"(d) : "l"(a), "l"(b), "l"(d));
}
static __device__ __forceinline__ float2 u2f(unsigned long long v) {
    float2 f;
    asm("mov.b64 {%0, %1}, %2;" : "=f"(f.x), "=f"(f.y) : "l"(v));
    return f;
}

extern __shared__ float sm[];

__global__ __launch_bounds__(THREADS, 2)
void tpl_kernel(const float* __restrict__ features,
                const float* __restrict__ radial,
                const float* __restrict__ angular,
                const float* __restrict__ W1,
                const float* __restrict__ b1,
                const float* __restrict__ W2,
                const float* __restrict__ b2,
                const float* __restrict__ Wa,
                const float* __restrict__ ba,
                float* __restrict__ out)
{
    float* Fs = sm;                       // [64][FSTR]  features tile, [i][t]
    float* Hs = sm + 64 * FSTR;           // [64][FSTR]  silu hidden,  [h][t]
    float* Wb = sm + 2 * 64 * FSTR;       // [2][4096]   W2-row double buffer

    const int tid  = threadIdx.x;
    const int t0   = blockIdx.x * TILE_T;
    const int warp = tid >> 5;            // o-group: owns outputs [warp*8, warp*8+8)
    const int lane = tid & 31;            // t-group: owns tokens  [lane*4, lane*4+4)
    const int o0   = warp << 3;
    const int tl   = lane << 2;

    // ---- Load F tile transposed: Fs[i][t] = features[t0+t][i] ----
    for (int e = tid; e < TILE_T * 64; e += THREADS) {
        int t = e >> 6, i = e & 63;
        Fs[i * FSTR + t] = features[(t0 + t) * 64 + i];
    }

    // ---- H = silu(radial @ W1 + b1), stored [h][t] ----
    for (int e = tid; e < TILE_T * 64; e += THREADS) {
        int t = e >> 6, h = e & 63;
        const float* rr = radial + (t0 + t) * 32;
        float acc = b1[h];
        #pragma unroll
        for (int r = 0; r < 32; ++r) acc += rr[r] * W1[r * 64 + h];
        float sg = 1.0f / (1.0f + expf(-acc));
        Hs[h * FSTR + t] = acc * sg;
    }

    // ---- Preload W2 row 0 into buffer 0 ----
    {
        const float4* src = reinterpret_cast<const float4*>(W2);
        float4* dst = reinterpret_cast<float4*>(Wb);
        #pragma unroll
        for (int j = 0; j < 4; ++j) dst[tid + j * THREADS] = src[tid + j * THREADS];
    }
    __syncthreads();

    // ---- Main loop: 65 K-chunks of 64 (h = 0..63, then bias chunk) ----
    unsigned long long acc[2][8];
    #pragma unroll
    for (int p = 0; p < 2; ++p)
        #pragma unroll
        for (int j = 0; j < 8; ++j) acc[p][j] = 0ull;

    for (int s = 0; s < 65; ++s) {
        // Prefetch next chunk's B row into registers (row s+1, or b2 for the bias chunk)
        float4 pre[4];
        if (s < 64) {
            const float* nsrc = (s + 1 < 64) ? (W2 + (s + 1) * 4096) : b2;
            const float4* src = reinterpret_cast<const float4*>(nsrc);
            #pragma unroll
            for (int j = 0; j < 4; ++j) pre[j] = src[tid + j * THREADS];
        }

        unsigned long long hp0, hp1;
        if (s < 64) {
            ulonglong2 hv = *reinterpret_cast<const ulonglong2*>(&Hs[s * FSTR + tl]);
            hp0 = hv.x; hp1 = hv.y;
        } else {
            hp0 = dup2(1.0f); hp1 = hp0;
        }

        const float* rbuf = Wb + (s & 1) * 4096;

        #pragma unroll 16
        for (int k = 0; k < 64; ++k) {
            ulonglong2 fv = *reinterpret_cast<const ulonglong2*>(&Fs[k * FSTR + tl]);
            unsigned long long u0 = mul2(hp0, fv.x);   // {h*f} for tokens tl+0, tl+1
            unsigned long long u1 = mul2(hp1, fv.y);   // {h*f} for tokens tl+2, tl+3

            const float* br = rbuf + (k << 6) + o0;
            float4 bA = *reinterpret_cast<const float4*>(br);
            float4 bB = *reinterpret_cast<const float4*>(br + 4);
            float bb[8] = {bA.x, bA.y, bA.z, bA.w, bB.x, bB.y, bB.z, bB.w};
            #pragma unroll
            for (int j = 0; j < 8; ++j) {
                unsigned long long d = dup2(bb[j]);
                fma2(acc[0][j], u0, d);
                fma2(acc[1][j], u1, d);
            }
        }

        if (s < 64) {
            float4* dst = reinterpret_cast<float4*>(Wb + ((s + 1) & 1) * 4096);
            #pragma unroll
            for (int j = 0; j < 4; ++j) dst[tid + j * THREADS] = pre[j];
        }
        __syncthreads();
    }

    // ---- Epilogue: out = acc * (angular @ Wa + ba) ----
    #pragma unroll
    for (int p = 0; p < 2; ++p) {
        #pragma unroll
        for (int sub = 0; sub < 2; ++sub) {
            int t = t0 + tl + 2 * p + sub;
            const float* arow = angular + t * 16;
            float av[8];
            #pragma unroll
            for (int j = 0; j < 8; ++j) av[j] = ba[o0 + j];
            #pragma unroll
            for (int a = 0; a < 16; ++a) {
                float aa = arow[a];
                #pragma unroll
                for (int j = 0; j < 8; ++j) av[j] += aa * Wa[a * 64 + o0 + j];
            }
            float res[8];
            #pragma unroll
            for (int j = 0; j < 8; ++j) {
                float2 v = u2f(acc[p][j]);
                res[j] = (sub ? v.y : v.x) * av[j];
            }
            float4* dst = reinterpret_cast<float4*>(out + t * 64 + o0);
            dst[0] = make_float4(res[0], res[1], res[2], res[3]);
            dst[1] = make_float4(res[4], res[5], res[6], res[7]);
        }
    }
}

extern "C" void kernel_launch(void* const* d_in, const int* in_sizes, int n_in,
                              void* d_out, int out_size)
{
    const float* features = (const float*)d_in[0];
    const float* radial   = (const float*)d_in[1];
    const float* angular  = (const float*)d_in[2];
    const float* W1       = (const float*)d_in[3];
    const float* b1       = (const float*)d_in[4];
    const float* W2       = (const float*)d_in[5];
    const float* b2       = (const float*)d_in[6];
    const float* Wa       = (const float*)d_in[7];
    const float* ba       = (const float*)d_in[8];
    float* out            = (float*)d_out;

    cudaFuncSetAttribute(tpl_kernel, cudaFuncAttributeMaxDynamicSharedMemorySize, SMEM_BYTES);
    tpl_kernel<<<NTOK / TILE_T, THREADS, SMEM_BYTES>>>(
        features, radial, angular, W1, b1, W2, b2, Wa, ba, out);
}

// round 4
// speedup vs baseline: 2.2854x; 2.2854x over previous
#include <cuda_runtime.h>
#include <math.h>
#include <stdint.h>

// TensorProductLayer — fused U-GEMM on mma.sync tf32 (m16n8k8), sm_100-safe.
//
//   out[t,o] = (sum_{h,i} H[t,h] F[t,i] W2[h, i*64+o] + sum_i F[t,i] b2[i*64+o])
//              * (angular@Wa + ba)[t,o]
//
// K = (h,i) = 65 chunks of 64 (h=0..63 + bias chunk with h==1).
// A-fragments (U) built in registers from resident F-frags * broadcast H.
// B chunks pre-rounded to tf32 and pre-permuted into per-lane fragment order
// so each k-step's B-frags load as 4 conflict-free LDS.128.

#define NTOK   65536
#define TPB    128
#define TILE   128
#define NGRID  (NTOK / TILE)     // 512
#define NCHUNK 65

// dynamic smem regions (bytes)
#define RA       0               // 34816: F stage (stride 68) -> Hs[65][128] -> D staging (stride 68)
#define RB       34816           // 32768: W1/b1 -> B chunk double buffer -> Wa/ba
#define SM_TOTAL (34816 + 32768) // 67584

__device__ float W2P[NCHUNK * 4096];   // packed tf32 B image (~1 MB, L2-resident)

// ---------- helpers ----------
static __device__ __forceinline__ uint32_t smem_u32(const void* p) {
    uint32_t a;
    asm("{ .reg .u64 t; cvta.to.shared.u64 t, %1; cvt.u32.u64 %0, t; }" : "=r"(a) : "l"(p));
    return a;
}
static __device__ __forceinline__ uint32_t cvt_tf32(float x) {
    uint32_t r; asm("cvt.rna.tf32.f32 %0, %1;" : "=r"(r) : "f"(x)); return r;
}
static __device__ __forceinline__ unsigned long long dup2(float x) {
    unsigned long long r; asm("mov.b64 %0, {%1, %1};" : "=l"(r) : "f"(x)); return r;
}
static __device__ __forceinline__ unsigned long long pack2(float a, float b) {
    unsigned long long r; asm("mov.b64 %0, {%1, %2};" : "=l"(r) : "f"(a), "f"(b)); return r;
}
static __device__ __forceinline__ void fma2(unsigned long long& d, unsigned long long a, unsigned long long b) {
    asm("fma.rn.f32x2 %0, %1, %2, %3;" : "=l"(d) : "l"(a), "l"(b), "l"(d));
}
static __device__ __forceinline__ float2 u2f(unsigned long long v) {
    float2 f; asm("mov.b64 {%0, %1}, %2;" : "=f"(f.x), "=f"(f.y) : "l"(v)); return f;
}

#define LDS128(v, addr) \
    asm volatile("ld.shared.v4.b32 {%0,%1,%2,%3}, [%4];" \
                 : "=r"((v).x), "=r"((v).y), "=r"((v).z), "=r"((v).w) : "r"(addr))

#define MMA(d, a, bb0, bb1) \
    asm volatile("mma.sync.aligned.m16n8k8.row.col.f32.tf32.tf32.f32 " \
                 "{%0,%1,%2,%3}, {%4,%5,%6,%7}, {%8,%9}, {%0,%1,%2,%3};" \
                 : "+f"((d)[0]), "+f"((d)[1]), "+f"((d)[2]), "+f"((d)[3]) \
                 : "r"((a)[0]), "r"((a)[1]), "r"((a)[2]), "r"((a)[3]), "r"(bb0), "r"(bb1))

#define CP16(dst, src) \
    asm volatile("cp.async.ca.shared.global [%0], [%1], 16;" :: "r"(dst), "l"(src))
#define CP_COMMIT() asm volatile("cp.async.commit_group;" ::: "memory")
#define CP_WAIT1()  asm volatile("cp.async.wait_group 1;" ::: "memory")
#define CP_WAIT0()  asm volatile("cp.async.wait_group 0;" ::: "memory")

// ---------- prep: tf32-round + fragment-permute W2 (+b2 as chunk 64) ----------
// dst layout per chunk: [kstep(8)][lane(32)][n(8)][half(2)] floats
//   value = src[i*64 + o], i = 8k + 4*half + (lane&3), o = 8n + (lane>>2)
__global__ void tpl_prep(const float* __restrict__ W2, const float* __restrict__ b2) {
    int s = blockIdx.x;
    const float* src = (s < 64) ? (W2 + s * 4096) : b2;
    for (int e = threadIdx.x; e < 4096; e += blockDim.x) {
        int k = e >> 9, lane = (e >> 4) & 31, n = (e >> 1) & 7, half = e & 1;
        int i = 8 * k + 4 * half + (lane & 3);
        int o = 8 * n + (lane >> 2);
        W2P[s * 4096 + e] = __uint_as_float(cvt_tf32(src[i * 64 + o]));
    }
}

// ---------- main ----------
extern __shared__ char smraw[];

static __device__ __forceinline__ void issue_chunk(uint32_t dstbase, int c, int tid) {
    #pragma unroll
    for (int j = 0; j < 8; ++j) {
        int idx = tid + j * TPB;
        CP16(dstbase + idx * 16, (const float4*)W2P + c * 1024 + idx);
    }
    CP_COMMIT();
}

__global__ __launch_bounds__(TPB, 2)
void tpl_main(const float* __restrict__ features,
              const float* __restrict__ radial,
              const float* __restrict__ angular,
              const float* __restrict__ W1,
              const float* __restrict__ b1,
              const float* __restrict__ Wa,
              const float* __restrict__ ba,
              float* __restrict__ out)
{
    const uint32_t sb = smem_u32(smraw);
    const int tid  = threadIdx.x;
    const int w    = tid >> 5;
    const int lane = tid & 31;
    const int tglob = blockIdx.x * TILE + tid;

    float* RAf = (float*)(smraw + RA);
    float* RBf = (float*)(smraw + RB);

    // ---- stage F tile (stride 68) + W1/b1 ----
    {
        const float4* fsrc = (const float4*)(features + (size_t)blockIdx.x * TILE * 64);
        for (int e = tid; e < TILE * 16; e += TPB) {
            int t = e >> 4, j = e & 15;
            *(float4*)(RAf + t * 68 + j * 4) = fsrc[e];
        }
        const float4* wsrc = (const float4*)W1;
        for (int e = tid; e < 512; e += TPB) ((float4*)RBf)[e] = wsrc[e];
        if (tid < 64) RBf[2048 + tid] = b1[tid];
    }
    __syncthreads();

    // ---- extract resident F fragments: ff[mtile][kstep][4] ----
    float ff[2][8][4];
    {
        int rA0 = (w << 5) + (lane >> 2);
        #pragma unroll
        for (int m = 0; m < 2; ++m) {
            int tA = rA0 + 16 * m, tB = tA + 8;
            #pragma unroll
            for (int k = 0; k < 8; ++k) {
                int c0 = 8 * k + (lane & 3);
                ff[m][k][0] = RAf[tA * 68 + c0];
                ff[m][k][1] = RAf[tB * 68 + c0];
                ff[m][k][2] = RAf[tA * 68 + c0 + 4];
                ff[m][k][3] = RAf[tB * 68 + c0 + 4];
            }
        }
    }
    // radial row for own token
    float rad[32];
    {
        const float4* r4 = (const float4*)(radial + (size_t)tglob * 32);
        #pragma unroll
        for (int j = 0; j < 8; ++j) {
            float4 v = r4[j];
            rad[4*j] = v.x; rad[4*j+1] = v.y; rad[4*j+2] = v.z; rad[4*j+3] = v.w;
        }
    }
    __syncthreads();   // F tile fully read; RA becomes Hs[65][128]

    // ---- H = silu(radial@W1 + b1) for own token -> Hs[s][t] ----
    {
        #pragma unroll
        for (int g = 0; g < 4; ++g) {
            unsigned long long acc8[8];
            #pragma unroll
            for (int j = 0; j < 8; ++j)
                acc8[j] = pack2(RBf[2048 + g*16 + 2*j], RBf[2048 + g*16 + 2*j + 1]);
            #pragma unroll
            for (int r = 0; r < 32; ++r) {
                unsigned long long rd = dup2(rad[r]);
                const unsigned long long* wp = (const unsigned long long*)(RBf + r*64 + g*16);
                #pragma unroll
                for (int j = 0; j < 8; ++j) fma2(acc8[j], rd, wp[j]);
            }
            #pragma unroll
            for (int j = 0; j < 8; ++j) {
                float2 v = u2f(acc8[j]);
                RAf[(g*16 + 2*j)     * 128 + tid] = v.x / (1.0f + expf(-v.x));
                RAf[(g*16 + 2*j + 1) * 128 + tid] = v.y / (1.0f + expf(-v.y));
            }
        }
        RAf[64 * 128 + tid] = 1.0f;   // bias chunk h
    }
    __syncthreads();   // Hs ready; RB free for B chunks

    // ---- prefetch B chunks 0,1 ----
    issue_chunk(sb + RB, 0, tid);
    issue_chunk(sb + RB + 16384, 1, tid);

    float acc[2][8][4];
    #pragma unroll
    for (int m = 0; m < 2; ++m)
        #pragma unroll
        for (int n = 0; n < 8; ++n)
            #pragma unroll
            for (int j = 0; j < 4; ++j) acc[m][n][j] = 0.0f;

    const int hbase = (w << 5) + (lane >> 2);

    for (int s = 0; s < NCHUNK; ++s) {
        const int p = s & 1;
        if (s < NCHUNK - 1) { CP_WAIT1(); } else { CP_WAIT0(); }
        __syncthreads();

        float h0 = RAf[s * 128 + hbase];
        float h1 = RAf[s * 128 + hbase + 8];
        float h2 = RAf[s * 128 + hbase + 16];
        float h3 = RAf[s * 128 + hbase + 24];

        const uint32_t bb = sb + RB + p * 16384 + (lane << 6);
        #pragma unroll
        for (int k = 0; k < 8; ++k) {
            uint4 b0, b1v, b2v, b3v;
            LDS128(b0,  bb + k * 2048);
            LDS128(b1v, bb + k * 2048 + 16);
            LDS128(b2v, bb + k * 2048 + 32);
            LDS128(b3v, bb + k * 2048 + 48);

            uint32_t a0[4], a1[4];
            a0[0] = cvt_tf32(h0 * ff[0][k][0]);
            a0[1] = cvt_tf32(h1 * ff[0][k][1]);
            a0[2] = cvt_tf32(h0 * ff[0][k][2]);
            a0[3] = cvt_tf32(h1 * ff[0][k][3]);
            a1[0] = cvt_tf32(h2 * ff[1][k][0]);
            a1[1] = cvt_tf32(h3 * ff[1][k][1]);
            a1[2] = cvt_tf32(h2 * ff[1][k][2]);
            a1[3] = cvt_tf32(h3 * ff[1][k][3]);

            MMA(acc[0][0], a0, b0.x,  b0.y);  MMA(acc[1][0], a1, b0.x,  b0.y);
            MMA(acc[0][1], a0, b0.z,  b0.w);  MMA(acc[1][1], a1, b0.z,  b0.w);
            MMA(acc[0][2], a0, b1v.x, b1v.y); MMA(acc[1][2], a1, b1v.x, b1v.y);
            MMA(acc[0][3], a0, b1v.z, b1v.w); MMA(acc[1][3], a1, b1v.z, b1v.w);
            MMA(acc[0][4], a0, b2v.x, b2v.y); MMA(acc[1][4], a1, b2v.x, b2v.y);
            MMA(acc[0][5], a0, b2v.z, b2v.w); MMA(acc[1][5], a1, b2v.z, b2v.w);
            MMA(acc[0][6], a0, b3v.x, b3v.y); MMA(acc[1][6], a1, b3v.x, b3v.y);
            MMA(acc[0][7], a0, b3v.z, b3v.w); MMA(acc[1][7], a1, b3v.z, b3v.w);
        }
        __syncthreads();
        if (s + 2 < NCHUNK) issue_chunk(sb + RB + p * 16384, s + 2, tid);
    }

    // ---- epilogue: frags -> RA staging (stride 68); Wa/ba -> RB ----
    {
        int rA0 = (w << 5) + (lane >> 2);
        int cq  = 2 * (lane & 3);
        #pragma unroll
        for (int m = 0; m < 2; ++m) {
            int tA = rA0 + 16 * m, tB = tA + 8;
            #pragma unroll
            for (int n = 0; n < 8; ++n) {
                *(float2*)(RAf + tA * 68 + 8 * n + cq) = make_float2(acc[m][n][0], acc[m][n][1]);
                *(float2*)(RAf + tB * 68 + 8 * n + cq) = make_float2(acc[m][n][2], acc[m][n][3]);
            }
        }
        const float4* wsrc = (const float4*)Wa;
        for (int e = tid; e < 256; e += TPB) ((float4*)RBf)[e] = wsrc[e];
        if (tid < 64) RBf[1024 + tid] = ba[tid];
    }
    __syncthreads();

    // ---- ang = angular@Wa + ba for own token; multiply; store ----
    {
        float ang[16];
        const float4* a4 = (const float4*)(angular + (size_t)tglob * 16);
        #pragma unroll
        for (int j = 0; j < 4; ++j) {
            float4 v = a4[j];
            ang[4*j] = v.x; ang[4*j+1] = v.y; ang[4*j+2] = v.z; ang[4*j+3] = v.w;
        }
        float4* orow = (float4*)(out + (size_t)tglob * 64);
        #pragma unroll
        for (int g = 0; g < 4; ++g) {
            unsigned long long acc8[8];
            #pragma unroll
            for (int j = 0; j < 8; ++j)
                acc8[j] = pack2(RBf[1024 + g*16 + 2*j], RBf[1024 + g*16 + 2*j + 1]);
            #pragma unroll
            for (int a = 0; a < 16; ++a) {
                unsigned long long ad = dup2(ang[a]);
                const unsigned long long* wp = (const unsigned long long*)(RBf + a*64 + g*16);
                #pragma unroll
                for (int j = 0; j < 8; ++j) fma2(acc8[j], ad, wp[j]);
            }
            float av[16];
            #pragma unroll
            for (int j = 0; j < 8; ++j) {
                float2 v = u2f(acc8[j]);
                av[2*j] = v.x; av[2*j+1] = v.y;
            }
            #pragma unroll
            for (int j = 0; j < 4; ++j) {
                float4 dv = *(float4*)(RAf + tid * 68 + g * 16 + j * 4);
                orow[g * 4 + j] = make_float4(dv.x * av[4*j], dv.y * av[4*j+1],
                                              dv.z * av[4*j+2], dv.w * av[4*j+3]);
            }
        }
    }
}

extern "C" void kernel_launch(void* const* d_in, const int* in_sizes, int n_in,
                              void* d_out, int out_size)
{
    const float* features = (const float*)d_in[0];
    const float* radial   = (const float*)d_in[1];
    const float* angular  = (const float*)d_in[2];
    const float* W1       = (const float*)d_in[3];
    const float* b1       = (const float*)d_in[4];
    const float* W2       = (const float*)d_in[5];
    const float* b2       = (const float*)d_in[6];
    const float* Wa       = (const float*)d_in[7];
    const float* ba       = (const float*)d_in[8];
    float* out            = (float*)d_out;

    tpl_prep<<<NCHUNK, 256>>>(W2, b2);

    cudaFuncSetAttribute(tpl_main, cudaFuncAttributeMaxDynamicSharedMemorySize, SM_TOTAL);
    tpl_main<<<NGRID, TPB, SM_TOTAL>>>(features, radial, angular, W1, b1, Wa, ba, out);
}